// round 11
// baseline (speedup 1.0000x reference)
#include <cuda_runtime.h>
#include <cuda_fp16.h>
#include <cstdint>

#define NF   40
#define ED   128
#define AD   128
#define NP   780     // 40*39/2
#define NPP  792     // scatter slack (dummy slot NP)
#define NTILE 103    // 100 rectangular 2x4 tiles + 3 diagonal tiles
#define NTHR 384     // 12 warps = 3 pair-groups x 4 a-slots
#define NWRP 12
#define XST  132     // padded row stride for x in smem (floats); 528B, 16B-aligned

__device__ __forceinline__ uint32_t h2pack(float lo, float hi) {
    __half2 h = __floats2half2_rn(lo, hi);   // .x = lo
    return *(uint32_t*)&h;
}

// D(m16n8) += A(m16k16, f16, row) * B(k16n8, f16, col), fp32 accum
__device__ __forceinline__ void mma16(float* d, const uint32_t* a, uint32_t b0, uint32_t b1) {
    asm volatile(
        "mma.sync.aligned.m16n8k16.row.col.f32.f16.f16.f32 "
        "{%0,%1,%2,%3}, {%4,%5,%6,%7}, {%8,%9}, {%0,%1,%2,%3};"
        : "+f"(d[0]), "+f"(d[1]), "+f"(d[2]), "+f"(d[3])
        : "r"(a[0]), "r"(a[1]), "r"(a[2]), "r"(a[3]), "r"(b0), "r"(b1));
}

// triu (i<j), i-major linear index
__device__ __forceinline__ int pair_idx(int i, int j) {
    return i * (2 * NF - i - 1) / 2 + (j - i - 1);
}

__global__ void __launch_bounds__(NTHR, 1)
afm_kernel(const float* __restrict__ x,    // [B, F, E]
           const float* __restrict__ ww,   // [A, E]
           const float* __restrict__ wb,   // [A]
           const float* __restrict__ hw,   // [1, A]
           const float* __restrict__ pw,   // [1, E]
           const float* __restrict__ pb,   // [1]
           float* __restrict__ out)        // [B]
{
    __shared__ float    xs[NF * XST];      // ~21.1 KB, row-major padded
    __shared__ float    scs4[4][NPP];      // per-aslot partial scores
    __shared__ float    scs[NPP];
    __shared__ float    dvs[NPP];          // d[p] = hp_p . p_w
    __shared__ float    pws[ED];
    __shared__ float2   swh[AD];           // (wb[a], hw[a])
    __shared__ uint8_t  qis[NTILE * 8], qjs[NTILE * 8];
    __shared__ uint16_t qps[NTILE * 8];
    __shared__ float    red[3 * NWRP];

    const int tid  = threadIdx.x;
    const int wid  = tid >> 5, lane = tid & 31;
    const int g     = wid >> 2;       // pair-group 0..2
    const int aslot = wid & 3;        // owns a-rows [aslot*32, +32)
    const int q = lane >> 2, c = lane & 3;
    const int b = blockIdx.x;

    // ---- Stage x (row-major, padded stride) ----
    const float* xg = x + (size_t)b * (NF * ED);
    for (int idx = tid; idx < NF * ED; idx += NTHR)
        xs[(idx >> 7) * XST + (idx & 127)] = xg[idx];
    for (int e = tid; e < ED; e += NTHR) pws[e] = pw[e];
    for (int a = tid; a < AD; a += NTHR) swh[a] = make_float2(wb[a], hw[a]);

    // ---- Tile tables: 2x4 rectangular blocks over the triangle ----
    // rowgroup a (i in {2a, 2a+1}), j-chunks of 4 in [2a+2, 40): cnt(a) = ceil((38-2a)/4)
    for (int t = tid; t < NTILE; t += NTHR) {
        if (t < 100) {
            int a = 0, rem = t;
            while (true) {
                int cnt = (41 - 2 * a) >> 2;
                if (rem < cnt) break;
                rem -= cnt; a++;
            }
            int jbase = 2 * a + 2 + 4 * rem;
            #pragma unroll
            for (int qq = 0; qq < 8; qq++) {
                int i = 2 * a + (qq >> 2);
                int j = jbase + (qq & 3);
                int idx = t * 8 + qq;
                if (j < NF) { qis[idx] = (uint8_t)i; qjs[idx] = (uint8_t)j; qps[idx] = (uint16_t)pair_idx(i, j); }
                else        { qis[idx] = 0; qjs[idx] = 1; qps[idx] = NP; }
            }
        } else {
            int d = t - 100;                // diagonal pairs (2a, 2a+1)
            #pragma unroll
            for (int qq = 0; qq < 8; qq++) {
                int a = d * 8 + qq;
                int idx = t * 8 + qq;
                if (a < 20) { qis[idx] = (uint8_t)(2 * a); qjs[idx] = (uint8_t)(2 * a + 1); qps[idx] = (uint16_t)pair_idx(2 * a, 2 * a + 1); }
                else        { qis[idx] = 0; qjs[idx] = 1; qps[idx] = NP; }
            }
        }
    }

    // ---- W fragments (register-stationary, fp16-packed), e-permuted:
    //      k16-step s: logical k {2c,2c+1,2c+8,2c+9} <-> e = 16s+4c + {0,1,2,3}
    const int A0 = aslot * 32;
    uint32_t wA[2][8][4];
    #pragma unroll
    for (int mt = 0; mt < 2; mt++) {
        #pragma unroll
        for (int s = 0; s < 8; s++) {
            int e0 = 16 * s + 4 * c;
            int r0 = (A0 + mt * 16 + q) * ED + e0;
            int r1 = r0 + 8 * ED;
            float4 w0 = *(const float4*)&ww[r0];
            float4 w1 = *(const float4*)&ww[r1];
            wA[mt][s][0] = h2pack(w0.x, w0.y);
            wA[mt][s][1] = h2pack(w1.x, w1.y);
            wA[mt][s][2] = h2pack(w0.z, w0.w);
            wA[mt][s][3] = h2pack(w1.z, w1.w);
        }
    }

    __syncthreads();

    // ---- Main loop: group g covers tiles [start[g], start[g+1]) ----
    const int nt0 = (g == 0) ? 0 : (g == 1 ? 35 : 69);
    const int nt1 = (g == 0) ? 35 : (g == 1 ? 69 : NTILE);

    for (int nt = nt0; nt < nt1; nt++) {
        const int tq = nt * 8 + q;
        const float* xi = &xs[(int)qis[tq] * XST + 4 * c];
        const float* xj = &xs[(int)qjs[tq] * XST + 4 * c];
        const bool do_d = (aslot == (nt & 3));    // round-robin d-duty

        // 4 independent accumulator chains: (m-tile 0/1) x (even/odd u)
        float accA0[4] = {0.f, 0.f, 0.f, 0.f};
        float accB0[4] = {0.f, 0.f, 0.f, 0.f};
        float accA1[4] = {0.f, 0.f, 0.f, 0.f};
        float accB1[4] = {0.f, 0.f, 0.f, 0.f};
        float dacc = 0.f;

        float4 vi = *(const float4*)&xi[0];
        float4 vj = *(const float4*)&xj[0];
        #pragma unroll
        for (int u = 0; u < 8; u++) {
            float4 cvi = vi, cvj = vj;
            if (u < 7) {
                vi = *(const float4*)&xi[16 * (u + 1)];
                vj = *(const float4*)&xj[16 * (u + 1)];
            }
            float p0 = cvi.x * cvj.x, p1 = cvi.y * cvj.y;
            float p2 = cvi.z * cvj.z, p3 = cvi.w * cvj.w;
            uint32_t b0 = h2pack(p0, p1);         // k = 2c, 2c+1
            uint32_t b1 = h2pack(p2, p3);         // k = 2c+8, 2c+9
            float* d0 = (u & 1) ? accB0 : accA0;
            float* d1 = (u & 1) ? accB1 : accA1;
            mma16(d0, wA[0][u], b0, b1);
            mma16(d1, wA[1][u], b0, b1);
            if (do_d) {
                float4 pw4 = *(const float4*)&pws[16 * u + 4 * c];
                dacc = fmaf(p0, pw4.x, fmaf(p1, pw4.y, fmaf(p2, pw4.z, fmaf(p3, pw4.w, dacc))));
            }
        }
        if (do_d) {
            dacc += __shfl_xor_sync(0xffffffffu, dacc, 1);
            dacc += __shfl_xor_sync(0xffffffffu, dacc, 2);
            int p = qps[tq];
            if (c == 0 && p < NP) dvs[p] = dacc;
        }

        float acc0[4], acc1[4];
        #pragma unroll
        for (int r = 0; r < 4; r++) {
            acc0[r] = accA0[r] + accB0[r];
            acc1[r] = accA1[r] + accB1[r];
        }

        // Fused epilogue: partial score = sum over this warp's 32 a of h*relu(.+wb)
        float s0 = 0.f, s1 = 0.f;
        #pragma unroll
        for (int u = 0; u < 4; u++) {
            float2 wh = swh[A0 + u * 8 + q];
            float au0 = (u < 2) ? acc0[2 * u]     : acc1[2 * (u - 2)];
            float au1 = (u < 2) ? acc0[2 * u + 1] : acc1[2 * (u - 2) + 1];
            s0 += fmaxf(au0 + wh.x, 0.f) * wh.y;
            s1 += fmaxf(au1 + wh.x, 0.f) * wh.y;
        }
        #pragma unroll
        for (int o = 4; o <= 16; o <<= 1) {
            s0 += __shfl_xor_sync(0xffffffffu, s0, o);
            s1 += __shfl_xor_sync(0xffffffffu, s1, o);
        }
        if (lane < 4) {
            scs4[aslot][qps[nt * 8 + 2 * lane]]     = s0;   // D col 2c
            scs4[aslot][qps[nt * 8 + 2 * lane + 1]] = s1;   // D col 2c+1
        }
    }
    __syncthreads();

    for (int p = tid; p < NP; p += NTHR)
        scs[p] = scs4[0][p] + scs4[1][p] + scs4[2][p] + scs4[3][p];
    __syncthreads();

    // ---- Softmax over pairs + weighted sum (h_b softmax-invariant, dropped) ----
    float lmax = -3.4e38f;
    for (int p = tid; p < NP; p += NTHR) lmax = fmaxf(lmax, scs[p]);
    #pragma unroll
    for (int o = 16; o; o >>= 1) lmax = fmaxf(lmax, __shfl_xor_sync(0xffffffffu, lmax, o));
    if (lane == 0) red[wid] = lmax;
    __syncthreads();
    float m = red[0];
    #pragma unroll
    for (int w = 1; w < NWRP; w++) m = fmaxf(m, red[w]);

    float se = 0.f, sd = 0.f;
    for (int p = tid; p < NP; p += NTHR) {
        float e = __expf(scs[p] - m);
        se += e;
        sd = fmaf(e, dvs[p], sd);
    }
    #pragma unroll
    for (int o = 16; o; o >>= 1) {
        se += __shfl_xor_sync(0xffffffffu, se, o);
        sd += __shfl_xor_sync(0xffffffffu, sd, o);
    }
    if (lane == 0) { red[NWRP + wid] = se; red[2 * NWRP + wid] = sd; }
    __syncthreads();
    if (tid == 0) {
        float S = 0.f, D = 0.f;
        #pragma unroll
        for (int w = 0; w < NWRP; w++) { S += red[NWRP + w]; D += red[2 * NWRP + w]; }
        out[b] = D / S + pb[0];
    }
}

extern "C" void kernel_launch(void* const* d_in, const int* in_sizes, int n_in,
                              void* d_out, int out_size) {
    const float* x  = (const float*)d_in[0];
    const float* ww = (const float*)d_in[1];
    const float* wb = (const float*)d_in[2];
    const float* hw = (const float*)d_in[3];
    // d_in[4] = attn_h_b: uniform shift on scores, softmax-invariant -> unused
    const float* pw = (const float*)d_in[5];
    const float* pb = (const float*)d_in[6];
    float* out = (float*)d_out;

    int B = in_sizes[0] / (NF * ED);
    afm_kernel<<<B, NTHR>>>(x, ww, wb, hw, pw, pb, out);
}

// round 12
// speedup vs baseline: 1.4209x; 1.4209x over previous
#include <cuda_runtime.h>
#include <cuda_fp16.h>
#include <cstdint>

#define NF   40
#define ED   128
#define AD   128
#define NP   780     // 40*39/2
#define NPP  784     // 98 n-tiles of 8 pairs
#define NTHR 384     // 12 warps = 3 pair-groups x 4 a-slots
#define NWRP 12
#define XSTH 136     // halves per x row in smem (272B = 17 x 16B, 16B-aligned rows)

__device__ __forceinline__ uint32_t h2pack(float lo, float hi) {
    __half2 h = __floats2half2_rn(lo, hi);   // .x = lo
    return *(uint32_t*)&h;
}
__device__ __forceinline__ uint32_t h2bits(__half2 h) { return *(uint32_t*)&h; }

// D(m16n8) += A(m16k16, f16, row) * B(k16n8, f16, col), fp32 accum
__device__ __forceinline__ void mma16(float* d, const uint32_t* a, uint32_t b0, uint32_t b1) {
    asm volatile(
        "mma.sync.aligned.m16n8k16.row.col.f32.f16.f16.f32 "
        "{%0,%1,%2,%3}, {%4,%5,%6,%7}, {%8,%9}, {%0,%1,%2,%3};"
        : "+f"(d[0]), "+f"(d[1]), "+f"(d[2]), "+f"(d[3])
        : "r"(a[0]), "r"(a[1]), "r"(a[2]), "r"(a[3]), "r"(b0), "r"(b1));
}

__global__ void __launch_bounds__(NTHR, 1)
afm_kernel(const float* __restrict__ x,    // [B, F, E]
           const float* __restrict__ ww,   // [A, E]
           const float* __restrict__ wb,   // [A]
           const float* __restrict__ hw,   // [1, A]
           const float* __restrict__ pw,   // [1, E]
           const float* __restrict__ pb,   // [1]
           float* __restrict__ out)        // [B]
{
    __shared__ __half  xsh[NF * XSTH];    // ~10.6 KB, fp16 x, padded rows
    __shared__ float   scs4[4][NPP];      // per-aslot partial scores
    __shared__ float   scs[NPP];
    __shared__ float   dvs[NPP];          // d[p] = hp_p . p_w
    __shared__ float   pws[ED];
    __shared__ float2  swh[AD];           // (wb[a], hw[a])
    __shared__ uint8_t pis[NPP], pjs[NPP];
    __shared__ float   red[3 * NWRP];

    const int tid  = threadIdx.x;
    const int wid  = tid >> 5, lane = tid & 31;
    const int g     = wid >> 2;       // pair-group 0..2
    const int aslot = wid & 3;        // owns a-rows [aslot*32, +32)
    const int q = lane >> 2, c = lane & 3;
    const int b = blockIdx.x;

    // ---- Stage x -> fp16 smem (padded stride) ----
    const float* xg = x + (size_t)b * (NF * ED);
    for (int idx = tid; idx < NF * (ED / 2); idx += NTHR) {
        int row = idx >> 6, pos = idx & 63;          // pos in half2 units
        float2 v = *(const float2*)&xg[row * ED + 2 * pos];
        *(__half2*)&xsh[row * XSTH + 2 * pos] = __floats2half2_rn(v.x, v.y);
    }
    for (int e = tid; e < ED; e += NTHR) pws[e] = pw[e];
    for (int a = tid; a < AD; a += NTHR) swh[a] = make_float2(wb[a], hw[a]);

    // ---- Pair index tables (triu i<j, i-major) ----
    for (int p = tid; p < NPP; p += NTHR) {
        if (p < NP) {
            int i = 0, rem = p;
            while (rem >= NF - 1 - i) { rem -= NF - 1 - i; i++; }
            pis[p] = (uint8_t)i; pjs[p] = (uint8_t)(i + 1 + rem);
        } else { pis[p] = 0; pjs[p] = 1; }
    }

    // ---- W fragments (register-stationary, fp16-packed), e-permuted:
    //      step s=2u+t: k{2c,2c+1} <-> e = 32u+8c+4t+{0,1};  k{2c+8,2c+9} <-> e+{2,3}
    const int A0 = aslot * 32;
    uint32_t wA[2][8][4];
    #pragma unroll
    for (int mt = 0; mt < 2; mt++) {
        #pragma unroll
        for (int s = 0; s < 8; s++) {
            int u = s >> 1, t = s & 1;
            int e0 = 32 * u + 8 * c + 4 * t;
            int r0 = (A0 + mt * 16 + q) * ED + e0;
            int r1 = r0 + 8 * ED;
            float4 w0 = *(const float4*)&ww[r0];
            float4 w1 = *(const float4*)&ww[r1];
            wA[mt][s][0] = h2pack(w0.x, w0.y);   // row q,   k{2c,2c+1}
            wA[mt][s][1] = h2pack(w1.x, w1.y);   // row q+8
            wA[mt][s][2] = h2pack(w0.z, w0.w);   // row q,   k{2c+8,2c+9}
            wA[mt][s][3] = h2pack(w1.z, w1.w);   // row q+8
        }
    }

    __syncthreads();

    // ---- Main loop: n-tiles of 8 pairs; group g covers [g*33, min(g*33+33, 98)) ----
    const int nt0 = g * 33;
    const int nt1 = (g == 2) ? 98 : nt0 + 33;

    for (int nt = nt0; nt < nt1; nt++) {
        const int p = nt * 8 + q;                 // this quad's pair (B col)
        const __half* xi = &xsh[(int)pis[p] * XSTH + 8 * c];
        const __half* xj = &xsh[(int)pjs[p] * XSTH + 8 * c];
        const bool do_d = (aslot == (nt & 3));    // round-robin d-duty

        // 4 independent accumulator chains: (m-tile 0/1) x (t=0/1)
        float accA0[4] = {0.f, 0.f, 0.f, 0.f};
        float accB0[4] = {0.f, 0.f, 0.f, 0.f};
        float accA1[4] = {0.f, 0.f, 0.f, 0.f};
        float accB1[4] = {0.f, 0.f, 0.f, 0.f};
        float dacc = 0.f;

        #pragma unroll
        for (int u = 0; u < 4; u++) {
            // one LDS.128 per operand: 8 halves = e [32u+8c, +8)
            uint4 vi = *(const uint4*)&xi[32 * u];
            uint4 vj = *(const uint4*)&xj[32 * u];
            __half2 p0 = __hmul2(*(__half2*)&vi.x, *(__half2*)&vj.x);  // e{0,1} = k{2c,2c+1}   (t=0)
            __half2 p1 = __hmul2(*(__half2*)&vi.y, *(__half2*)&vj.y);  // e{2,3} = k{2c+8,2c+9} (t=0)
            __half2 p2 = __hmul2(*(__half2*)&vi.z, *(__half2*)&vj.z);  // e{4,5} = k{2c,2c+1}   (t=1)
            __half2 p3 = __hmul2(*(__half2*)&vi.w, *(__half2*)&vj.w);  // e{6,7} = k{2c+8,2c+9} (t=1)
            mma16(accA0, wA[0][2 * u],     h2bits(p0), h2bits(p1));
            mma16(accA1, wA[1][2 * u],     h2bits(p0), h2bits(p1));
            mma16(accB0, wA[0][2 * u + 1], h2bits(p2), h2bits(p3));
            mma16(accB1, wA[1][2 * u + 1], h2bits(p2), h2bits(p3));
            if (do_d) {
                float2 f0 = __half22float2(p0), f1 = __half22float2(p1);
                float2 f2 = __half22float2(p2), f3 = __half22float2(p3);
                const float* pwp = &pws[32 * u + 8 * c];
                float4 pa = *(const float4*)&pwp[0];
                float4 pb4 = *(const float4*)&pwp[4];
                dacc = fmaf(f0.x, pa.x, fmaf(f0.y, pa.y, fmaf(f1.x, pa.z, fmaf(f1.y, pa.w, dacc))));
                dacc = fmaf(f2.x, pb4.x, fmaf(f2.y, pb4.y, fmaf(f3.x, pb4.z, fmaf(f3.y, pb4.w, dacc))));
            }
        }
        if (do_d) {
            dacc += __shfl_xor_sync(0xffffffffu, dacc, 1);
            dacc += __shfl_xor_sync(0xffffffffu, dacc, 2);
            if (c == 0 && p < NP) dvs[p] = dacc;
        }

        float acc0[4], acc1[4];
        #pragma unroll
        for (int r = 0; r < 4; r++) {
            acc0[r] = accA0[r] + accB0[r];
            acc1[r] = accA1[r] + accB1[r];
        }

        // Fused epilogue: partial score = sum over this warp's 32 a of h*relu(.+wb)
        float s0 = 0.f, s1 = 0.f;
        #pragma unroll
        for (int u = 0; u < 4; u++) {
            float2 wh = swh[A0 + u * 8 + q];
            float au0 = (u < 2) ? acc0[2 * u]     : acc1[2 * (u - 2)];
            float au1 = (u < 2) ? acc0[2 * u + 1] : acc1[2 * (u - 2) + 1];
            s0 += fmaxf(au0 + wh.x, 0.f) * wh.y;
            s1 += fmaxf(au1 + wh.x, 0.f) * wh.y;
        }
        #pragma unroll
        for (int o = 4; o <= 16; o <<= 1) {
            s0 += __shfl_xor_sync(0xffffffffu, s0, o);
            s1 += __shfl_xor_sync(0xffffffffu, s1, o);
        }
        if (lane < 4) {
            scs4[aslot][nt * 8 + 2 * lane]     = s0;
            scs4[aslot][nt * 8 + 2 * lane + 1] = s1;
        }
    }
    __syncthreads();

    for (int p = tid; p < NP; p += NTHR)
        scs[p] = scs4[0][p] + scs4[1][p] + scs4[2][p] + scs4[3][p];
    __syncthreads();

    // ---- Softmax over pairs + weighted sum (h_b softmax-invariant, dropped) ----
    float lmax = -3.4e38f;
    for (int p = tid; p < NP; p += NTHR) lmax = fmaxf(lmax, scs[p]);
    #pragma unroll
    for (int o = 16; o; o >>= 1) lmax = fmaxf(lmax, __shfl_xor_sync(0xffffffffu, lmax, o));
    if (lane == 0) red[wid] = lmax;
    __syncthreads();
    float m = red[0];
    #pragma unroll
    for (int w = 1; w < NWRP; w++) m = fmaxf(m, red[w]);

    float se = 0.f, sd = 0.f;
    for (int p = tid; p < NP; p += NTHR) {
        float e = __expf(scs[p] - m);
        se += e;
        sd = fmaf(e, dvs[p], sd);
    }
    #pragma unroll
    for (int o = 16; o; o >>= 1) {
        se += __shfl_xor_sync(0xffffffffu, se, o);
        sd += __shfl_xor_sync(0xffffffffu, sd, o);
    }
    if (lane == 0) { red[NWRP + wid] = se; red[2 * NWRP + wid] = sd; }
    __syncthreads();
    if (tid == 0) {
        float S = 0.f, D = 0.f;
        #pragma unroll
        for (int w = 0; w < NWRP; w++) { S += red[NWRP + w]; D += red[2 * NWRP + w]; }
        out[b] = D / S + pb[0];
    }
}

extern "C" void kernel_launch(void* const* d_in, const int* in_sizes, int n_in,
                              void* d_out, int out_size) {
    const float* x  = (const float*)d_in[0];
    const float* ww = (const float*)d_in[1];
    const float* wb = (const float*)d_in[2];
    const float* hw = (const float*)d_in[3];
    // d_in[4] = attn_h_b: uniform shift on scores, softmax-invariant -> unused
    const float* pw = (const float*)d_in[5];
    const float* pb = (const float*)d_in[6];
    float* out = (float*)d_out;

    int B = in_sizes[0] / (NF * ED);
    afm_kernel<<<B, NTHR>>>(x, ww, wb, hw, pw, pb, out);
}

// round 13
// speedup vs baseline: 1.6025x; 1.1278x over previous
#include <cuda_runtime.h>
#include <cuda_fp16.h>
#include <cstdint>

#define NF   40
#define ED   128
#define AD   128
#define NP   780     // 40*39/2
#define NPP  784     // 98 n-tiles of 8 pairs
#define NTHR 512     // 16 warps = 4 pair-groups x 4 a-slots
#define NWRP 16
#define XSTH 136     // halves per x row in smem (272B = 17 x 16B, 16B-aligned rows)

__device__ __forceinline__ uint32_t h2pack(float lo, float hi) {
    __half2 h = __floats2half2_rn(lo, hi);   // .x = lo
    return *(uint32_t*)&h;
}
__device__ __forceinline__ uint32_t h2bits(__half2 h) { return *(uint32_t*)&h; }

// D(m16n8) += A(m16k16, f16, row) * B(k16n8, f16, col), fp32 accum
__device__ __forceinline__ void mma16(float* d, const uint32_t* a, uint32_t b0, uint32_t b1) {
    asm volatile(
        "mma.sync.aligned.m16n8k16.row.col.f32.f16.f16.f32 "
        "{%0,%1,%2,%3}, {%4,%5,%6,%7}, {%8,%9}, {%0,%1,%2,%3};"
        : "+f"(d[0]), "+f"(d[1]), "+f"(d[2]), "+f"(d[3])
        : "r"(a[0]), "r"(a[1]), "r"(a[2]), "r"(a[3]), "r"(b0), "r"(b1));
}

__global__ void __launch_bounds__(NTHR, 1)
afm_kernel(const float* __restrict__ x,    // [B, F, E]
           const float* __restrict__ ww,   // [A, E]
           const float* __restrict__ wb,   // [A]
           const float* __restrict__ hw,   // [1, A]
           const float* __restrict__ pw,   // [1, E]
           const float* __restrict__ pb,   // [1]
           float* __restrict__ out)        // [B]
{
    __shared__ __half  xsh[NF * XSTH];    // ~10.6 KB, fp16 x, padded rows
    __shared__ float   scs4[4][NPP];      // per-aslot partial scores
    __shared__ float   scs[NPP];
    __shared__ float   dvs[NPP];          // d[p] = hp_p . p_w
    __shared__ float   pws[ED];
    __shared__ float2  swh[AD];           // (wb[a], hw[a])
    __shared__ uint8_t pis[NPP], pjs[NPP];
    __shared__ float   red[3 * NWRP];

    const int tid  = threadIdx.x;
    const int wid  = tid >> 5, lane = tid & 31;
    const int g     = wid >> 2;       // pair-group 0..3
    const int aslot = wid & 3;        // owns a-rows [aslot*32, +32)
    const int q = lane >> 2, c = lane & 3;
    const int b = blockIdx.x;

    // ---- Stage x -> fp16 smem (padded stride) ----
    const float* xg = x + (size_t)b * (NF * ED);
    for (int idx = tid; idx < NF * (ED / 2); idx += NTHR) {
        int row = idx >> 6, pos = idx & 63;          // pos in half2 units
        float2 v = *(const float2*)&xg[row * ED + 2 * pos];
        *(__half2*)&xsh[row * XSTH + 2 * pos] = __floats2half2_rn(v.x, v.y);
    }
    for (int e = tid; e < ED; e += NTHR) pws[e] = pw[e];
    for (int a = tid; a < AD; a += NTHR) swh[a] = make_float2(wb[a], hw[a]);

    // ---- Pair index tables (triu i<j, i-major) ----
    for (int p = tid; p < NPP; p += NTHR) {
        if (p < NP) {
            int i = 0, rem = p;
            while (rem >= NF - 1 - i) { rem -= NF - 1 - i; i++; }
            pis[p] = (uint8_t)i; pjs[p] = (uint8_t)(i + 1 + rem);
        } else { pis[p] = 0; pjs[p] = 1; }
    }

    // ---- W fragments (register-stationary, fp16-packed), e-permuted:
    //      step s=2u+t: k{2c,2c+1} <-> e = 32u+8c+4t+{0,1};  k{2c+8,2c+9} <-> e+{2,3}
    const int A0 = aslot * 32;
    uint32_t wA[2][8][4];
    #pragma unroll
    for (int mt = 0; mt < 2; mt++) {
        #pragma unroll
        for (int s = 0; s < 8; s++) {
            int u = s >> 1, t = s & 1;
            int e0 = 32 * u + 8 * c + 4 * t;
            int r0 = (A0 + mt * 16 + q) * ED + e0;
            int r1 = r0 + 8 * ED;
            float4 w0 = *(const float4*)&ww[r0];
            float4 w1 = *(const float4*)&ww[r1];
            wA[mt][s][0] = h2pack(w0.x, w0.y);   // row q,   k{2c,2c+1}
            wA[mt][s][1] = h2pack(w1.x, w1.y);   // row q+8
            wA[mt][s][2] = h2pack(w0.z, w0.w);   // row q,   k{2c+8,2c+9}
            wA[mt][s][3] = h2pack(w1.z, w1.w);   // row q+8
        }
    }

    __syncthreads();

    // ---- Main loop: 98 tiles split 25/25/24/24 across 4 groups ----
    const int nt0 = (g < 2) ? g * 25 : 50 + (g - 2) * 24;
    const int nt1 = nt0 + ((g < 2) ? 25 : 24);

    for (int nt = nt0; nt < nt1; nt++) {
        const int p = nt * 8 + q;                 // this quad's pair (B col)
        const __half* xi = &xsh[(int)pis[p] * XSTH + 8 * c];
        const __half* xj = &xsh[(int)pjs[p] * XSTH + 8 * c];
        const bool do_d = (aslot == (nt & 3));    // round-robin d-duty

        // 4 independent accumulator chains: (m-tile 0/1) x (t=0/1)
        float accA0[4] = {0.f, 0.f, 0.f, 0.f};
        float accB0[4] = {0.f, 0.f, 0.f, 0.f};
        float accA1[4] = {0.f, 0.f, 0.f, 0.f};
        float accB1[4] = {0.f, 0.f, 0.f, 0.f};
        float dacc = 0.f;

        #pragma unroll
        for (int u = 0; u < 4; u++) {
            // one LDS.128 per operand: 8 halves = e [32u+8c, +8)
            uint4 vi = *(const uint4*)&xi[32 * u];
            uint4 vj = *(const uint4*)&xj[32 * u];
            __half2 p0 = __hmul2(*(__half2*)&vi.x, *(__half2*)&vj.x);
            __half2 p1 = __hmul2(*(__half2*)&vi.y, *(__half2*)&vj.y);
            __half2 p2 = __hmul2(*(__half2*)&vi.z, *(__half2*)&vj.z);
            __half2 p3 = __hmul2(*(__half2*)&vi.w, *(__half2*)&vj.w);
            mma16(accA0, wA[0][2 * u],     h2bits(p0), h2bits(p1));
            mma16(accA1, wA[1][2 * u],     h2bits(p0), h2bits(p1));
            mma16(accB0, wA[0][2 * u + 1], h2bits(p2), h2bits(p3));
            mma16(accB1, wA[1][2 * u + 1], h2bits(p2), h2bits(p3));
            if (do_d) {
                float2 f0 = __half22float2(p0), f1 = __half22float2(p1);
                float2 f2 = __half22float2(p2), f3 = __half22float2(p3);
                const float* pwp = &pws[32 * u + 8 * c];
                float4 pa = *(const float4*)&pwp[0];
                float4 pb4 = *(const float4*)&pwp[4];
                dacc = fmaf(f0.x, pa.x, fmaf(f0.y, pa.y, fmaf(f1.x, pa.z, fmaf(f1.y, pa.w, dacc))));
                dacc = fmaf(f2.x, pb4.x, fmaf(f2.y, pb4.y, fmaf(f3.x, pb4.z, fmaf(f3.y, pb4.w, dacc))));
            }
        }
        if (do_d) {
            dacc += __shfl_xor_sync(0xffffffffu, dacc, 1);
            dacc += __shfl_xor_sync(0xffffffffu, dacc, 2);
            if (c == 0 && p < NP) dvs[p] = dacc;
        }

        // Fused epilogue (acc merge folded in): sum over this warp's 32 a of h*relu(.+wb)
        float s0 = 0.f, s1 = 0.f;
        #pragma unroll
        for (int u = 0; u < 4; u++) {
            float2 wh = swh[A0 + u * 8 + q];
            float au0 = (u < 2) ? (accA0[2 * u] + accB0[2 * u])
                                : (accA1[2 * (u - 2)] + accB1[2 * (u - 2)]);
            float au1 = (u < 2) ? (accA0[2 * u + 1] + accB0[2 * u + 1])
                                : (accA1[2 * (u - 2) + 1] + accB1[2 * (u - 2) + 1]);
            s0 += fmaxf(au0 + wh.x, 0.f) * wh.y;
            s1 += fmaxf(au1 + wh.x, 0.f) * wh.y;
        }
        #pragma unroll
        for (int o = 4; o <= 16; o <<= 1) {
            s0 += __shfl_xor_sync(0xffffffffu, s0, o);
            s1 += __shfl_xor_sync(0xffffffffu, s1, o);
        }
        if (lane < 4) {
            scs4[aslot][nt * 8 + 2 * lane]     = s0;
            scs4[aslot][nt * 8 + 2 * lane + 1] = s1;
        }
    }
    __syncthreads();

    for (int p = tid; p < NP; p += NTHR)
        scs[p] = scs4[0][p] + scs4[1][p] + scs4[2][p] + scs4[3][p];
    __syncthreads();

    // ---- Softmax over pairs + weighted sum (h_b softmax-invariant, dropped) ----
    float lmax = -3.4e38f;
    for (int p = tid; p < NP; p += NTHR) lmax = fmaxf(lmax, scs[p]);
    #pragma unroll
    for (int o = 16; o; o >>= 1) lmax = fmaxf(lmax, __shfl_xor_sync(0xffffffffu, lmax, o));
    if (lane == 0) red[wid] = lmax;
    __syncthreads();
    float m = red[0];
    #pragma unroll
    for (int w = 1; w < NWRP; w++) m = fmaxf(m, red[w]);

    float se = 0.f, sd = 0.f;
    for (int p = tid; p < NP; p += NTHR) {
        float e = __expf(scs[p] - m);
        se += e;
        sd = fmaf(e, dvs[p], sd);
    }
    #pragma unroll
    for (int o = 16; o; o >>= 1) {
        se += __shfl_xor_sync(0xffffffffu, se, o);
        sd += __shfl_xor_sync(0xffffffffu, sd, o);
    }
    if (lane == 0) { red[NWRP + wid] = se; red[2 * NWRP + wid] = sd; }
    __syncthreads();
    if (tid == 0) {
        float S = 0.f, D = 0.f;
        #pragma unroll
        for (int w = 0; w < NWRP; w++) { S += red[NWRP + w]; D += red[2 * NWRP + w]; }
        out[b] = D / S + pb[0];
    }
}

extern "C" void kernel_launch(void* const* d_in, const int* in_sizes, int n_in,
                              void* d_out, int out_size) {
    const float* x  = (const float*)d_in[0];
    const float* ww = (const float*)d_in[1];
    const float* wb = (const float*)d_in[2];
    const float* hw = (const float*)d_in[3];
    // d_in[4] = attn_h_b: uniform shift on scores, softmax-invariant -> unused
    const float* pw = (const float*)d_in[5];
    const float* pb = (const float*)d_in[6];
    float* out = (float*)d_out;

    int B = in_sizes[0] / (NF * ED);
    afm_kernel<<<B, NTHR>>>(x, ww, wb, hw, pw, pb, out);
}

// round 14
// speedup vs baseline: 1.6169x; 1.0090x over previous
#include <cuda_runtime.h>
#include <cuda_fp16.h>
#include <cstdint>

#define NF   40
#define ED   128
#define AD   128
#define NP   780     // 40*39/2
#define NPP  784     // 98 n-tiles of 8 pairs
#define NTHR 512     // 16 warps = 4 pair-groups x 4 a-slots
#define NWRP 16
#define XSTH 136     // halves per x row in smem (272B = 17 x 16B, 16B-aligned rows)

__device__ __forceinline__ uint32_t h2pack(float lo, float hi) {
    __half2 h = __floats2half2_rn(lo, hi);   // .x = lo
    return *(uint32_t*)&h;
}
__device__ __forceinline__ uint32_t h2bits(__half2 h) { return *(uint32_t*)&h; }

// D(m16n8) += A(m16k16, f16, row) * B(k16n8, f16, col), fp32 accum
__device__ __forceinline__ void mma16(float* d, const uint32_t* a, uint32_t b0, uint32_t b1) {
    asm volatile(
        "mma.sync.aligned.m16n8k16.row.col.f32.f16.f16.f32 "
        "{%0,%1,%2,%3}, {%4,%5,%6,%7}, {%8,%9}, {%0,%1,%2,%3};"
        : "+f"(d[0]), "+f"(d[1]), "+f"(d[2]), "+f"(d[3])
        : "r"(a[0]), "r"(a[1]), "r"(a[2]), "r"(a[3]), "r"(b0), "r"(b1));
}

__global__ void __launch_bounds__(NTHR, 1)
afm_kernel(const float* __restrict__ x,    // [B, F, E]
           const float* __restrict__ ww,   // [A, E]
           const float* __restrict__ wb,   // [A]
           const float* __restrict__ hw,   // [1, A]
           const float* __restrict__ pw,   // [1, E]
           const float* __restrict__ pb,   // [1]
           float* __restrict__ out)        // [B]
{
    __shared__ __half  xsh[NF * XSTH];    // ~10.6 KB, fp16 x, padded rows
    __shared__ __half  pwh[ED];           // fp16 p_w
    __shared__ float   scs4[4][NPP];      // per-aslot partial scores
    __shared__ float   scs[NPP];
    __shared__ float   dvs[NPP];          // d[p] = hp_p . p_w
    __shared__ uint8_t pis[NPP], pjs[NPP];
    __shared__ float   red[3 * NWRP];

    const int tid  = threadIdx.x;
    const int wid  = tid >> 5, lane = tid & 31;
    const int g     = wid >> 2;       // pair-group 0..3
    const int aslot = wid & 3;        // owns a-rows [aslot*32, +32)
    const int q = lane >> 2, c = lane & 3;
    const int b = blockIdx.x;

    // ---- Stage x -> fp16 smem (padded stride) ----
    const float* xg = x + (size_t)b * (NF * ED);
    for (int idx = tid; idx < NF * (ED / 2); idx += NTHR) {
        int row = idx >> 6, pos = idx & 63;          // pos in half2 units
        float2 v = *(const float2*)&xg[row * ED + 2 * pos];
        *(__half2*)&xsh[row * XSTH + 2 * pos] = __floats2half2_rn(v.x, v.y);
    }
    for (int e = tid; e < ED; e += NTHR) pwh[e] = __float2half_rn(pw[e]);

    // ---- Pair index tables (triu i<j, i-major) ----
    for (int p = tid; p < NPP; p += NTHR) {
        if (p < NP) {
            int i = 0, rem = p;
            while (rem >= NF - 1 - i) { rem -= NF - 1 - i; i++; }
            pis[p] = (uint8_t)i; pjs[p] = (uint8_t)(i + 1 + rem);
        } else { pis[p] = 0; pjs[p] = 1; }
    }

    // ---- W fragments (register-stationary, fp16-packed), e-permuted:
    //      step s=2u+t: k{2c,2c+1} <-> e = 32u+8c+4t+{0,1};  k{2c+8,2c+9} <-> e+{2,3}
    const int A0 = aslot * 32;
    uint32_t wA[2][8][4];
    #pragma unroll
    for (int mt = 0; mt < 2; mt++) {
        #pragma unroll
        for (int s = 0; s < 8; s++) {
            int u = s >> 1, t = s & 1;
            int e0 = 32 * u + 8 * c + 4 * t;
            int r0 = (A0 + mt * 16 + q) * ED + e0;
            int r1 = r0 + 8 * ED;
            float4 w0 = *(const float4*)&ww[r0];
            float4 w1 = *(const float4*)&ww[r1];
            wA[mt][s][0] = h2pack(w0.x, w0.y);   // row q,   k{2c,2c+1}
            wA[mt][s][1] = h2pack(w1.x, w1.y);   // row q+8
            wA[mt][s][2] = h2pack(w0.z, w0.w);   // row q,   k{2c+8,2c+9}
            wA[mt][s][3] = h2pack(w1.z, w1.w);   // row q+8
        }
    }
    // Hoisted (wb, h) per (u, q): 4 persistent half2 regs
    uint32_t whr[4];
    #pragma unroll
    for (int u = 0; u < 4; u++) {
        int a = A0 + u * 8 + q;
        whr[u] = h2pack(__ldg(&wb[a]), __ldg(&hw[a]));
    }

    __syncthreads();

    // ---- Main loop: 98 tiles split 25/25/24/24 across 4 groups ----
    const int nt0 = (g < 2) ? g * 25 : 50 + (g - 2) * 24;
    const int nt1 = nt0 + ((g < 2) ? 25 : 24);

    for (int nt = nt0; nt < nt1; nt++) {
        const int p = nt * 8 + q;                 // this quad's pair (B col)
        const __half* xi = &xsh[(int)pis[p] * XSTH + 8 * c];
        const __half* xj = &xsh[(int)pjs[p] * XSTH + 8 * c];
        const bool do_d = (aslot == (nt & 3));    // round-robin d-duty

        // 4 independent accumulator chains: (m-tile 0/1) x (t=0/1)
        float accA0[4] = {0.f, 0.f, 0.f, 0.f};
        float accB0[4] = {0.f, 0.f, 0.f, 0.f};
        float accA1[4] = {0.f, 0.f, 0.f, 0.f};
        float accB1[4] = {0.f, 0.f, 0.f, 0.f};
        float dacc = 0.f;

        #pragma unroll
        for (int u = 0; u < 4; u++) {
            // one LDS.128 per operand: 8 halves = e [32u+8c, +8)
            uint4 vi = *(const uint4*)&xi[32 * u];
            uint4 vj = *(const uint4*)&xj[32 * u];
            __half2 p0 = __hmul2(*(__half2*)&vi.x, *(__half2*)&vj.x);
            __half2 p1 = __hmul2(*(__half2*)&vi.y, *(__half2*)&vj.y);
            __half2 p2 = __hmul2(*(__half2*)&vi.z, *(__half2*)&vj.z);
            __half2 p3 = __hmul2(*(__half2*)&vi.w, *(__half2*)&vj.w);
            mma16(accA0, wA[0][2 * u],     h2bits(p0), h2bits(p1));
            mma16(accA1, wA[1][2 * u],     h2bits(p0), h2bits(p1));
            mma16(accB0, wA[0][2 * u + 1], h2bits(p2), h2bits(p3));
            mma16(accB1, wA[1][2 * u + 1], h2bits(p2), h2bits(p3));
            if (do_d) {
                uint4 vp = *(const uint4*)&pwh[32 * u + 8 * c];   // 8 fp16 pw
                float2 f0 = __half22float2(p0), f1 = __half22float2(p1);
                float2 f2 = __half22float2(p2), f3 = __half22float2(p3);
                float2 w0 = __half22float2(*(__half2*)&vp.x);
                float2 w1 = __half22float2(*(__half2*)&vp.y);
                float2 w2 = __half22float2(*(__half2*)&vp.z);
                float2 w3 = __half22float2(*(__half2*)&vp.w);
                dacc = fmaf(f0.x, w0.x, fmaf(f0.y, w0.y, fmaf(f1.x, w1.x, fmaf(f1.y, w1.y, dacc))));
                dacc = fmaf(f2.x, w2.x, fmaf(f2.y, w2.y, fmaf(f3.x, w3.x, fmaf(f3.y, w3.y, dacc))));
            }
        }
        if (do_d) {
            dacc += __shfl_xor_sync(0xffffffffu, dacc, 1);
            dacc += __shfl_xor_sync(0xffffffffu, dacc, 2);
            if (c == 0 && p < NP) dvs[p] = dacc;
        }

        // Fused epilogue: sum over this warp's 32 a of h*relu(.+wb), using hoisted (wb,h)
        float s0 = 0.f, s1 = 0.f;
        #pragma unroll
        for (int u = 0; u < 4; u++) {
            float2 wh = __half22float2(*(__half2*)&whr[u]);   // (wb, h)
            float au0 = (u < 2) ? (accA0[2 * u] + accB0[2 * u])
                                : (accA1[2 * (u - 2)] + accB1[2 * (u - 2)]);
            float au1 = (u < 2) ? (accA0[2 * u + 1] + accB0[2 * u + 1])
                                : (accA1[2 * (u - 2) + 1] + accB1[2 * (u - 2) + 1]);
            s0 += fmaxf(au0 + wh.x, 0.f) * wh.y;
            s1 += fmaxf(au1 + wh.x, 0.f) * wh.y;
        }
        #pragma unroll
        for (int o = 4; o <= 16; o <<= 1) {
            s0 += __shfl_xor_sync(0xffffffffu, s0, o);
            s1 += __shfl_xor_sync(0xffffffffu, s1, o);
        }
        if (lane < 4) {
            scs4[aslot][nt * 8 + 2 * lane]     = s0;
            scs4[aslot][nt * 8 + 2 * lane + 1] = s1;
        }
    }
    __syncthreads();

    for (int p = tid; p < NP; p += NTHR)
        scs[p] = scs4[0][p] + scs4[1][p] + scs4[2][p] + scs4[3][p];
    __syncthreads();

    // ---- Softmax over pairs + weighted sum (h_b softmax-invariant, dropped) ----
    float lmax = -3.4e38f;
    for (int p = tid; p < NP; p += NTHR) lmax = fmaxf(lmax, scs[p]);
    #pragma unroll
    for (int o = 16; o; o >>= 1) lmax = fmaxf(lmax, __shfl_xor_sync(0xffffffffu, lmax, o));
    if (lane == 0) red[wid] = lmax;
    __syncthreads();
    float m = red[0];
    #pragma unroll
    for (int w = 1; w < NWRP; w++) m = fmaxf(m, red[w]);

    float se = 0.f, sd = 0.f;
    for (int p = tid; p < NP; p += NTHR) {
        float e = __expf(scs[p] - m);
        se += e;
        sd = fmaf(e, dvs[p], sd);
    }
    #pragma unroll
    for (int o = 16; o; o >>= 1) {
        se += __shfl_xor_sync(0xffffffffu, se, o);
        sd += __shfl_xor_sync(0xffffffffu, sd, o);
    }
    if (lane == 0) { red[NWRP + wid] = se; red[2 * NWRP + wid] = sd; }
    __syncthreads();
    if (tid == 0) {
        float S = 0.f, D = 0.f;
        #pragma unroll
        for (int w = 0; w < NWRP; w++) { S += red[NWRP + w]; D += red[2 * NWRP + w]; }
        out[b] = D / S + pb[0];
    }
}

extern "C" void kernel_launch(void* const* d_in, const int* in_sizes, int n_in,
                              void* d_out, int out_size) {
    const float* x  = (const float*)d_in[0];
    const float* ww = (const float*)d_in[1];
    const float* wb = (const float*)d_in[2];
    const float* hw = (const float*)d_in[3];
    // d_in[4] = attn_h_b: uniform shift on scores, softmax-invariant -> unused
    const float* pw = (const float*)d_in[5];
    const float* pb = (const float*)d_in[6];
    float* out = (float*)d_out;

    int B = in_sizes[0] / (NF * ED);
    afm_kernel<<<B, NTHR>>>(x, ww, wb, hw, pw, pb, out);
}